// round 14
// baseline (speedup 1.0000x reference)
#include <cuda_runtime.h>
#include <cstdint>

#define B_    8
#define F_IN  32
#define CN    256
#define M_    64
#define C_OUT 64
#define C_CAT 224   // (2*3+1)*32

// piece0 only: x^T tf32-rounded, [bm][f][n]
__device__ float g_X[(size_t)B_ * M_ * F_IN * CN];

// ================= helpers =================
__device__ __forceinline__ uint32_t smem_u32(const void* p) {
    uint32_t a;
    asm("{ .reg .u64 t; cvta.to.shared.u64 t, %1; cvt.u32.u64 %0, t; }" : "=r"(a) : "l"(p));
    return a;
}
__device__ __forceinline__ void cp_async16_pol(uint32_t sa, const void* g, uint64_t pol) {
    asm volatile("cp.async.cg.shared.global.L2::cache_hint [%0], [%1], 16, %2;\n"
                 :: "r"(sa), "l"(g), "l"(pol));
}
__device__ __forceinline__ void cp_commit() { asm volatile("cp.async.commit_group;\n"); }
template<int N> __device__ __forceinline__ void cp_wait() {
    asm volatile("cp.async.wait_group %0;\n" :: "n"(N));
}
__device__ __forceinline__ uint32_t f2tf32(float f) {
    uint32_t u; asm("cvt.rna.tf32.f32 %0, %1;" : "=r"(u) : "f"(f)); return u;
}
__device__ __forceinline__ uint32_t lds32(uint32_t a) {
    uint32_t v; asm("ld.shared.b32 %0, [%1];" : "=r"(v) : "r"(a)); return v;
}
__device__ __forceinline__ void sts32(uint32_t a, uint32_t v) {
    asm volatile("st.shared.b32 [%0], %1;" :: "r"(a), "r"(v));
}
__device__ __forceinline__ uint64_t mk_policy_evict_last() {
    uint64_t pol;
    asm("createpolicy.fractional.L2::evict_last.b64 %0, 1.0;" : "=l"(pol));
    return pol;
}
__device__ __forceinline__ void mma_tf32(float c[4], const uint32_t a[4],
                                         uint32_t b0, uint32_t b1) {
    asm volatile("mma.sync.aligned.m16n8k8.row.col.f32.tf32.tf32.f32 "
                 "{%0,%1,%2,%3},{%4,%5,%6,%7},{%8,%9},{%0,%1,%2,%3};"
                 : "+f"(c[0]), "+f"(c[1]), "+f"(c[2]), "+f"(c[3])
                 : "r"(a[0]), "r"(a[1]), "r"(a[2]), "r"(a[3]), "r"(b0), "r"(b1));
}

// ================= Kernel 1: x[b,f,n,m] -> g_X[bm][f][n], tf32-rounded =================
__global__ __launch_bounds__(256) void k_transpose(const float* __restrict__ x) {
    int id = blockIdx.x;           // ((b*32 + f)*8 + nt)
    int nt = id & 7;
    int f  = (id >> 3) & 31;
    int b  = id >> 8;

    __shared__ float ts[32][65];
    int t  = threadIdx.x;
    int m  = t & 63;
    int nl = t >> 6;               // 0..3
    const float* xp = x + ((size_t)(b * F_IN + f) * CN + nt * 32) * M_;
#pragma unroll
    for (int i = 0; i < 8; ++i) {
        int r = nl + 4 * i;
        ts[r][m] = xp[(size_t)r * M_ + m];
    }
    __syncthreads();
    int nl2 = t & 31;
    int mg  = t >> 5;              // 0..7
#pragma unroll
    for (int i = 0; i < 8; ++i) {
        int mm = mg + 8 * i;
        __stcs(&g_X[((size_t)(b * M_ + mm) * F_IN + f) * CN + nt * 32 + nl2],
               __uint_as_float(f2tf32(ts[nl2][mm])));
    }
}

// ================= Kernel 2: fully fused GCN block =================
// One CTA per (b,m). For each base: hop1 D=A^T x, hop2 D=A^T x1; every piece is
// immediately folded into register-resident y_acc[64o x 32c-per-warp] via a
// K=32 contribution GEMM against W. Pieces never touch DRAM.
//
// smem layout (bytes):
//   XS0: [f=32][n stride 260] tf32       33,280 @ 0        (piece0, immutable)
//   XS1: same shape                       33,280 @ 33280    (x1, rebuilt per base)
//   AS : 4 x [n=16][v stride 260] fp32    66,560 @ 66560
//   DB : [v=256][f stride 36] tf32        36,864 @ 133120
//   WS : [o=64][fc stride 228] tf32       58,368 @ 169984
#define SM_XS0 0u
#define SM_XS1 33280u
#define SM_AS  66560u
#define AS_BUF 16640u
#define SM_DB  133120u
#define SM_WS  169984u
#define SM_TOT 228352u

__device__ __forceinline__ void stage_chunk(const float* __restrict__ Ag, uint64_t pol,
                                            uint32_t sb, int rowg, int col4,
                                            int idx16, int buf) {
    const float* src = Ag + (size_t)(idx16 * 16) * CN;
    uint32_t dst = sb + SM_AS + (uint32_t)buf * AS_BUF;
#pragma unroll
    for (int k = 0; k < 4; ++k) {
        int row = rowg + 4 * k;
        cp_async16_pol(dst + (uint32_t)(row * 260 + col4) * 4u, src + row * CN + col4, pol);
    }
}

// y_acc += W[:, piece*32 : piece*32+32] . B   (B[k=f][n=c], per-warp c-range)
__device__ __forceinline__ void contrib_piece(float (&yac)[4][4][4], uint32_t wsA, int piece,
                                              uint32_t bB, uint32_t ntS, uint32_t ksS,
                                              uint32_t b1o) {
#pragma unroll
    for (int ks = 0; ks < 4; ++ks) {
        uint32_t kofs = (uint32_t)(piece * 32 + 8 * ks) * 4u;
        uint32_t a[4][4], bb[4][2];
#pragma unroll
        for (int mt = 0; mt < 4; ++mt) {
            uint32_t ab = wsA + (uint32_t)mt * 14592u + kofs;
            a[mt][0] = lds32(ab);            // (o0+r,   k+cq)
            a[mt][1] = lds32(ab + 7296u);    // (o0+r+8, k+cq)
            a[mt][2] = lds32(ab + 16u);      // (o0+r,   k+cq+4)
            a[mt][3] = lds32(ab + 7312u);
        }
#pragma unroll
        for (int nt = 0; nt < 4; ++nt) {
            uint32_t bx = bB + (uint32_t)nt * ntS + (uint32_t)ks * ksS;
            bb[nt][0] = lds32(bx);
            bb[nt][1] = lds32(bx + b1o);
        }
#pragma unroll
        for (int mt = 0; mt < 4; ++mt)
#pragma unroll
            for (int nt = 0; nt < 4; ++nt)
                mma_tf32(yac[mt][nt], a[mt], bb[nt][0], bb[nt][1]);
    }
}

__global__ __launch_bounds__(256, 1) void k_fused(const float* __restrict__ b0,
                                                  const float* __restrict__ b1,
                                                  const float* __restrict__ b2,
                                                  const float* __restrict__ W,
                                                  const float* __restrict__ bias,
                                                  float* __restrict__ y)
{
    extern __shared__ char smem[];
    uint32_t sb = smem_u32(smem);
    int t   = threadIdx.x;
    int wid = t >> 5;
    int l   = t & 31;
    int r   = l >> 2;
    int cq  = l & 3;

    int bm = blockIdx.x;            // 0..511
    int b  = bm >> 6;
    int m  = bm & 63;
    const float* Ab0 = b0 + (size_t)bm * (CN * CN);
    const float* Ab1 = b1 + (size_t)bm * (CN * CN);
    const float* Ab2 = b2 + (size_t)bm * (CN * CN);

    uint64_t pol = mk_policy_evict_last();
    int rowg = t >> 6;
    int col4 = (t & 63) * 4;

    // ---- prologue: stage A chunks 0,1,2 of base 0 ----
    stage_chunk(Ab0, pol, sb, rowg, col4, 0, 0); cp_commit();
    stage_chunk(Ab0, pol, sb, rowg, col4, 1, 1); cp_commit();
    stage_chunk(Ab0, pol, sb, rowg, col4, 2, 2); cp_commit();

    // xs0 <- g_X piece0 (already tf32 bits)
    {
        uint32_t* xsw = (uint32_t*)(smem + SM_XS0);
        const uint32_t* src = (const uint32_t*)(g_X + (size_t)bm * (F_IN * CN));
#pragma unroll
        for (int k = 0; k < 32; ++k) {
            int idx = t + 256 * k;
            int f = idx >> 8, n = idx & 255;
            xsw[f * 260 + n] = src[idx];
        }
    }
    // Ws <- tf32(W)
    {
        uint32_t* wsw = (uint32_t*)(smem + SM_WS);
        for (int i = t; i < C_OUT * C_CAT; i += 256) {
            int o = i / C_CAT, fc = i % C_CAT;
            wsw[o * 228 + fc] = f2tf32(W[i]);
        }
    }
    float bv0[4], bv1[4];
#pragma unroll
    for (int mt = 0; mt < 4; ++mt) {
        bv0[mt] = bias[16 * mt + r];
        bv1[mt] = bias[16 * mt + r + 8];
    }
    __syncthreads();

    // ---- accumulators ----
    float yac[4][4][4];
#pragma unroll
    for (int mt = 0; mt < 4; ++mt)
#pragma unroll
        for (int nt = 0; nt < 4; ++nt)
#pragma unroll
            for (int e = 0; e < 4; ++e) yac[mt][nt][e] = 0.0f;
    float acc[2][4][4];
#pragma unroll
    for (int mt = 0; mt < 2; ++mt)
#pragma unroll
        for (int nt = 0; nt < 4; ++nt)
#pragma unroll
            for (int e = 0; e < 4; ++e) acc[mt][nt][e] = 0.0f;

    // fragment bases
    uint32_t wsA   = sb + SM_WS + (uint32_t)(r * 228 + cq) * 4u;
    uint32_t baseA = (uint32_t)(cq * 260 + 32 * wid + r) * 4u;               // As buffer-local
    uint32_t hopB  = (uint32_t)(r * 260 + cq) * 4u;                          // + XS0/XS1
    uint32_t dbB   = sb + SM_DB + (uint32_t)((32 * wid + r) * 36 + cq) * 4u; // contribution B (Dbuf)
    uint32_t p0B   = sb + SM_XS0 + (uint32_t)(cq * 260 + 32 * wid + r) * 4u; // contribution B (piece0)

    // piece0 contribution (overlaps with in-flight A staging)
    contrib_piece(yac, wsA, 0, p0B, 32u, 8320u, 4160u);

    // ---- main loop: 3 bases x 2 hops x 16 chunks ----
    for (int j = 0; j < 96; ++j) {
        if (j < 94)       cp_wait<2>();
        else if (j == 94) cp_wait<1>();
        else              cp_wait<0>();
        __syncthreads();

        if (j + 3 < 96) {
            int nj = j + 3;
            const float* Ag = (nj >> 5) == 0 ? Ab0 : ((nj >> 5) == 1 ? Ab1 : Ab2);
            stage_chunk(Ag, pol, sb, rowg, col4, (nj & 31) & 15, nj & 3);
            cp_commit();
        }

        // hop MMA on As buf (j&3); B from xs0 (hop1) or xs1 (hop2)
        {
            uint32_t abase = sb + SM_AS + (uint32_t)(j & 3) * AS_BUF + baseA;
            uint32_t bbase = sb + (((j & 31) < 16) ? SM_XS0 : SM_XS1) + hopB;
            uint32_t nb4   = (uint32_t)(16 * (j & 15)) * 4u;
#pragma unroll
            for (int ks = 0; ks < 2; ++ks) {
                uint32_t a0[2][4], bb[4][2];
#pragma unroll
                for (int mt = 0; mt < 2; ++mt) {
                    uint32_t ab = abase + (uint32_t)mt * 64u + (uint32_t)ks * 8320u;
                    a0[mt][0] = f2tf32(__uint_as_float(lds32(ab)));
                    a0[mt][1] = f2tf32(__uint_as_float(lds32(ab + 32u)));
                    a0[mt][2] = f2tf32(__uint_as_float(lds32(ab + 4160u)));
                    a0[mt][3] = f2tf32(__uint_as_float(lds32(ab + 4192u)));
                }
#pragma unroll
                for (int nt = 0; nt < 4; ++nt) {
                    uint32_t bx = bbase + (uint32_t)nt * 8320u + nb4 + (uint32_t)ks * 32u;
                    bb[nt][0] = lds32(bx);
                    bb[nt][1] = lds32(bx + 16u);
                }
#pragma unroll
                for (int mt = 0; mt < 2; ++mt)
#pragma unroll
                    for (int nt = 0; nt < 4; ++nt)
                        mma_tf32(acc[mt][nt], a0[mt], bb[nt][0], bb[nt][1]);
            }
        }

        int jp = j & 31;
        if (jp == 15 || jp == 31) {
            int kb = j >> 5;
            int piece = (jp == 15) ? (1 + 2 * kb) : (2 + 2 * kb);
            // store tf32-rounded D into Dbuf [v][f] stride 36 (per-warp rows)
#pragma unroll
            for (int mt = 0; mt < 2; ++mt)
#pragma unroll
                for (int nt = 0; nt < 4; ++nt) {
                    int v0 = 32 * wid + 16 * mt + r;
                    int f0 = 8 * nt + 2 * cq;
                    uint32_t a0 = sb + SM_DB + (uint32_t)(v0 * 36 + f0) * 4u;
                    uint32_t a1 = sb + SM_DB + (uint32_t)((v0 + 8) * 36 + f0) * 4u;
                    sts32(a0,      f2tf32(acc[mt][nt][0]));
                    sts32(a0 + 4u, f2tf32(acc[mt][nt][1]));
                    sts32(a1,      f2tf32(acc[mt][nt][2]));
                    sts32(a1 + 4u, f2tf32(acc[mt][nt][3]));
                }
            __syncthreads();   // Dbuf complete (rebuild reads cross-warp rows)

            // fold piece into y_acc
            contrib_piece(yac, wsA, piece, dbB, 1152u, 32u, 16u);

            if (jp == 15) {
                // rebuild xs1[f][n] <- Dbuf[n][f] (already tf32 bits)
                uint32_t* xsw = (uint32_t*)(smem + SM_XS1);
                const uint32_t* db = (const uint32_t*)(smem + SM_DB);
                int f = l;
#pragma unroll
                for (int k = 0; k < 32; ++k) {
                    int n = wid + 8 * k;
                    xsw[f * 260 + n] = db[n * 36 + f];
                }
            }
            __syncthreads();   // xs1 ready / Dbuf consumers done

#pragma unroll
            for (int mt = 0; mt < 2; ++mt)
#pragma unroll
                for (int nt = 0; nt < 4; ++nt)
#pragma unroll
                    for (int e = 0; e < 4; ++e) acc[mt][nt][e] = 0.0f;
        }
    }

    // ---- epilogue: y[((b*64+o)*256+c)*64 + m] ----
#pragma unroll
    for (int mt = 0; mt < 4; ++mt)
#pragma unroll
        for (int nt = 0; nt < 4; ++nt) {
            int o0 = 16 * mt + r;
            int c0 = 32 * wid + 8 * nt + 2 * cq;
            y[((size_t)(b * C_OUT + o0) * CN + c0) * M_ + m]         = yac[mt][nt][0] + bv0[mt];
            y[((size_t)(b * C_OUT + o0) * CN + c0 + 1) * M_ + m]     = yac[mt][nt][1] + bv0[mt];
            y[((size_t)(b * C_OUT + o0 + 8) * CN + c0) * M_ + m]     = yac[mt][nt][2] + bv1[mt];
            y[((size_t)(b * C_OUT + o0 + 8) * CN + c0 + 1) * M_ + m] = yac[mt][nt][3] + bv1[mt];
        }
}

// ================= launch =================
extern "C" void kernel_launch(void* const* d_in, const int* in_sizes, int n_in,
                              void* d_out, int out_size) {
    const float* x    = (const float*)d_in[0];
    const float* b0   = (const float*)d_in[1];
    const float* b1   = (const float*)d_in[2];
    const float* b2   = (const float*)d_in[3];
    const float* W    = (const float*)d_in[4];
    const float* bias = (const float*)d_in[5];
    float* y = (float*)d_out;

    cudaFuncSetAttribute(k_fused, cudaFuncAttributeMaxDynamicSharedMemorySize, (int)SM_TOT);

    k_transpose<<<2048, 256>>>(x);
    k_fused<<<512, 256, SM_TOT>>>(b0, b1, b2, W, bias, y);
}